// round 2
// baseline (speedup 1.0000x reference)
#include <cuda_runtime.h>
#include <cstdint>

#define NUM_CLASSES 80
#define PRE_NMS_K   400
#define MAX_BOXES   200
#define NMS_THRESH  0.6f
#define BATCH       8
#define NANCH       16128   // 64*64*3 + 32*32*3 + 16*16*3
#define FLAT_K      (NUM_CLASSES * PRE_NMS_K)   // 32000

// ---- device scratch (no allocations allowed) ----
__device__ float g_boxes[BATCH * NANCH * 4];                    // (y1,x1,y2,x2) clipped
__device__ float g_scores[BATCH * NUM_CLASSES * NANCH];         // [b][c][n]
__device__ float g_kept_scores[BATCH * NUM_CLASSES * PRE_NMS_K];
__device__ float g_kept_boxes[BATCH * NUM_CLASSES * PRE_NMS_K * 4];

__device__ __forceinline__ float sigmoidf(float x) {
    return 1.0f / (1.0f + expf(-x));
}

// ============================================================
// Kernel 1: decode all levels
// ============================================================
__global__ __launch_bounds__(256) void decode_kernel(
    const float* __restrict__ p3, const float* __restrict__ p4, const float* __restrict__ p5,
    const float* __restrict__ a3, const float* __restrict__ a4, const float* __restrict__ a5)
{
    int t = blockIdx.x * blockDim.x + threadIdx.x;
    if (t >= BATCH * NANCH) return;
    int b = t / NANCH;
    int n = t - b * NANCH;

    const float* p; const float* anc;
    int HW; float stride, sxy; int loc;
    if (n < 12288)      { p = p3; anc = a3; HW = 64; stride = 8.0f;  sxy = 1.20f; loc = n; }
    else if (n < 15360) { p = p4; anc = a4; HW = 32; stride = 16.0f; sxy = 1.10f; loc = n - 12288; }
    else                { p = p5; anc = a5; HW = 16; stride = 32.0f; sxy = 1.05f; loc = n - 15360; }

    int a  = loc % 3;
    int hw = loc / 3;
    int w  = hw % HW;
    int h  = hw / HW;

    const float* q = p + ((size_t)((b * HW + h) * HW + w)) * (3 * (NUM_CLASSES + 5)) + a * (NUM_CLASSES + 5);

    float tx = q[0], ty = q[1], tw = q[2], th = q[3], tobj = q[4];
    float invHW = 1.0f / (float)HW;

    float sx = sigmoidf(tx);
    float sy = sigmoidf(ty);
    float x = (sx * sxy - 0.5f * (sxy - 1.0f) + (float)w) * invHW;
    float y = (sy * sxy - 0.5f * (sxy - 1.0f) + (float)h) * invHW;

    float denom = 1.0f / ((float)HW * stride);
    float bw = expf(tw) * anc[a * 2 + 0] * denom;
    float bh = expf(th) * anc[a * 2 + 1] * denom;

    float y1 = fminf(fmaxf(y - 0.5f * bh, 0.0f), 1.0f);
    float x1 = fminf(fmaxf(x - 0.5f * bw, 0.0f), 1.0f);
    float y2 = fminf(fmaxf(y + 0.5f * bh, 0.0f), 1.0f);
    float x2 = fminf(fmaxf(x + 0.5f * bw, 0.0f), 1.0f);

    float* bo = g_boxes + ((size_t)b * NANCH + n) * 4;
    bo[0] = y1; bo[1] = x1; bo[2] = y2; bo[3] = x2;

    float obj = sigmoidf(tobj);
    float* so = g_scores + (size_t)b * NUM_CLASSES * NANCH + n;
#pragma unroll 16
    for (int c = 0; c < NUM_CLASSES; c++) {
        so[(size_t)c * NANCH] = sigmoidf(q[5 + c]) * obj;
    }
}

// ============================================================
// Radix-select: exact K-th largest value (as uint bits) over n
// positive floats. Leaves K-th largest bit pattern in *sh_prefix.
// ============================================================
__device__ void radix_kth(const float* __restrict__ sc, int n, int K,
                          unsigned* sh_hist, unsigned* sh_prefix, int* sh_rem)
{
    int tid = threadIdx.x;
    if (tid == 0) { *sh_prefix = 0u; *sh_rem = K; }
    __syncthreads();
    for (int shift = 24; shift >= 0; shift -= 8) {
        for (int i = tid; i < 256; i += blockDim.x) sh_hist[i] = 0u;
        __syncthreads();
        unsigned pref = *sh_prefix;
        for (int i = tid; i < n; i += blockDim.x) {
            unsigned k = __float_as_uint(sc[i]);
            bool m = (shift == 24) ? true : ((k >> (shift + 8)) == pref);
            if (m) atomicAdd(&sh_hist[(k >> shift) & 255u], 1u);
        }
        __syncthreads();
        if (tid == 0) {
            int rem = *sh_rem;
            unsigned cum = 0; int bkt = 0;
            for (int bb = 255; bb >= 0; --bb) {
                unsigned hh = sh_hist[bb];
                if (cum + hh >= (unsigned)rem) { bkt = bb; break; }
                cum += hh;
            }
            *sh_prefix = (pref << 8) | (unsigned)bkt;
            *sh_rem = rem - (int)cum;
        }
        __syncthreads();
    }
}

// descending bitonic sort of SIZE u64 keys, key = (valbits<<32) | (~idx)
template <int SIZE>
__device__ void bitonic_desc(unsigned long long* a)
{
    int tid = threadIdx.x;
    for (int k = 2; k <= SIZE; k <<= 1) {
        for (int j = k >> 1; j > 0; j >>= 1) {
            __syncthreads();
            for (int i = tid; i < SIZE; i += blockDim.x) {
                int ixj = i ^ j;
                if (ixj > i) {
                    bool seg = (i & k) == 0;   // descending segment
                    unsigned long long x = a[i], y = a[ixj];
                    if (seg ? (x < y) : (x > y)) { a[i] = y; a[ixj] = x; }
                }
            }
        }
    }
    __syncthreads();
}

// ============================================================
// Kernel 2: per (b, class) top-400 + greedy NMS
// grid = BATCH*NUM_CLASSES blocks, 256 threads
// ============================================================
__global__ __launch_bounds__(256) void percls_kernel()
{
    __shared__ unsigned hist[256];
    __shared__ unsigned s_prefix;
    __shared__ int s_rem;
    __shared__ unsigned long long cand[1024];
    __shared__ int s_cnt;
    __shared__ float bx0[PRE_NMS_K], bx1[PRE_NMS_K], bx2[PRE_NMS_K], bx3[PRE_NMS_K], ar[PRE_NMS_K];
    __shared__ unsigned mat[PRE_NMS_K][13];
    __shared__ unsigned keepw[13];

    int tid = threadIdx.x;
    int bc = blockIdx.x;
    int b = bc / NUM_CLASSES;
    const float* sc = g_scores + (size_t)bc * NANCH;

    radix_kth(sc, NANCH, PRE_NMS_K, hist, &s_prefix, &s_rem);
    unsigned T = s_prefix;

    if (tid == 0) s_cnt = 0;
    __syncthreads();
    for (int i = tid; i < NANCH; i += 256) {
        unsigned k = __float_as_uint(sc[i]);
        if (k >= T) {
            int p = atomicAdd(&s_cnt, 1);
            if (p < 1024)
                cand[p] = ((unsigned long long)k << 32) | (unsigned long long)(0xFFFFFFFFu - (unsigned)i);
        }
    }
    __syncthreads();
    int cnt = min(s_cnt, 1024);
    for (int i = tid; i < 1024; i += 256)
        if (i >= cnt) cand[i] = 0ULL;
    bitonic_desc<1024>(cand);

    // gather boxes of top-400 (sorted), zero suppression matrix
    for (int t = tid; t < PRE_NMS_K; t += 256) {
        unsigned idx = 0xFFFFFFFFu - (unsigned)(cand[t] & 0xFFFFFFFFull);
        const float* bp = g_boxes + ((size_t)b * NANCH + idx) * 4;
        float y1 = bp[0], x1 = bp[1], y2 = bp[2], x2 = bp[3];
        bx0[t] = y1; bx1[t] = x1; bx2[t] = y2; bx3[t] = x2;
        ar[t] = (y2 - y1) * (x2 - x1);
    }
    for (int i = tid; i < PRE_NMS_K * 13; i += 256) ((unsigned*)mat)[i] = 0u;
    __syncthreads();

    // suppression bitmask: mat[i] marks j>i with IoU>thresh
    for (int p = tid; p < PRE_NMS_K * PRE_NMS_K; p += 256) {
        int i = p / PRE_NMS_K;
        int j = p - i * PRE_NMS_K;
        if (j > i) {
            float ty = fmaxf(bx0[i], bx0[j]);
            float tx = fmaxf(bx1[i], bx1[j]);
            float by = fminf(bx2[i], bx2[j]);
            float rx = fminf(bx3[i], bx3[j]);
            float hh = fmaxf(by - ty, 0.0f);
            float ww = fmaxf(rx - tx, 0.0f);
            float inter = hh * ww;
            float uni = ar[i] + ar[j] - inter;
            float iou = inter / fmaxf(uni, 1e-9f);
            if (iou > NMS_THRESH)
                atomicOr(&mat[i][j >> 5], 1u << (j & 31));
        }
    }
    __syncthreads();

    // serial greedy sweep on warp 0 (400 bits = 12 full words + 16 bits)
    if (tid < 32) {
        unsigned kw = (tid < 12) ? 0xFFFFFFFFu : ((tid == 12) ? 0xFFFFu : 0u);
        for (int i = 0; i < PRE_NMS_K; i++) {
            unsigned wb = __shfl_sync(0xFFFFFFFFu, kw, i >> 5);
            if ((wb >> (i & 31)) & 1u) {
                if (tid < 13) kw &= ~mat[i][tid];
            }
        }
        if (tid < 13) keepw[tid] = kw;
    }
    __syncthreads();

    float* ks = g_kept_scores + (size_t)bc * PRE_NMS_K;
    float* kb = g_kept_boxes + (size_t)bc * PRE_NMS_K * 4;
    for (int t = tid; t < PRE_NMS_K; t += 256) {
        float v = __uint_as_float((unsigned)(cand[t] >> 32));
        int kept = (keepw[t >> 5] >> (t & 31)) & 1;
        ks[t] = (kept && v > 0.0f) ? v : 0.0f;
        kb[t * 4 + 0] = bx0[t];
        kb[t * 4 + 1] = bx1[t];
        kb[t * 4 + 2] = bx2[t];
        kb[t * 4 + 3] = bx3[t];
    }
}

// ============================================================
// Kernel 3: per-image top-200 over 80*400 kept scores
// grid = BATCH, 256 threads
// out layout (float32): bbox[8][200][4] | conf[8][200] | cls[8][200] | num[8]
// ============================================================
__global__ __launch_bounds__(256) void final_kernel(float* __restrict__ out)
{
    __shared__ unsigned hist[256];
    __shared__ unsigned s_prefix;
    __shared__ int s_rem;
    __shared__ unsigned long long cand[512];
    __shared__ int s_cnt, s_nval;

    int tid = threadIdx.x;
    int b = blockIdx.x;
    const float* sc = g_kept_scores + (size_t)b * FLAT_K;

    radix_kth(sc, FLAT_K, MAX_BOXES, hist, &s_prefix, &s_rem);
    unsigned T = s_prefix;

    if (tid == 0) { s_cnt = 0; s_nval = 0; }
    __syncthreads();
    for (int i = tid; i < FLAT_K; i += 256) {
        unsigned k = __float_as_uint(sc[i]);
        bool take = (T > 0u) ? (k >= T) : (k > 0u);
        if (take) {
            int p = atomicAdd(&s_cnt, 1);
            if (p < 512)
                cand[p] = ((unsigned long long)k << 32) | (unsigned long long)(0xFFFFFFFFu - (unsigned)i);
        }
    }
    __syncthreads();
    int cnt = min(s_cnt, 512);
    for (int i = tid; i < 512; i += 256)
        if (i >= cnt) cand[i] = 0ULL;
    bitonic_desc<512>(cand);

    for (int t = tid; t < MAX_BOXES; t += 256) {
        unsigned long long e = cand[t];
        float v = __uint_as_float((unsigned)(e >> 32));
        bool valid = v > 0.0f;
        unsigned flat = 0xFFFFFFFFu - (unsigned)(e & 0xFFFFFFFFull);
        float b0 = 0.f, b1 = 0.f, b2 = 0.f, b3 = 0.f;
        float clsf = 0.f;
        if (valid) {
            const float* kb = g_kept_boxes + ((size_t)b * FLAT_K + flat) * 4;
            b0 = kb[0]; b1 = kb[1]; b2 = kb[2]; b3 = kb[3];
            clsf = (float)(flat / PRE_NMS_K);
            atomicAdd(&s_nval, 1);
        }
        int o = b * MAX_BOXES + t;
        out[o * 4 + 0] = b0;
        out[o * 4 + 1] = b1;
        out[o * 4 + 2] = b2;
        out[o * 4 + 3] = b3;
        out[BATCH * MAX_BOXES * 4 + o] = v;
        out[BATCH * MAX_BOXES * 4 + BATCH * MAX_BOXES + o] = clsf;
    }
    __syncthreads();
    if (tid == 0)
        out[BATCH * MAX_BOXES * 4 + 2 * BATCH * MAX_BOXES + b] = (float)s_nval;
}

// ============================================================
extern "C" void kernel_launch(void* const* d_in, const int* in_sizes, int n_in,
                              void* d_out, int out_size)
{
    const float* p3 = (const float*)d_in[0];
    const float* p4 = (const float*)d_in[1];
    const float* p5 = (const float*)d_in[2];
    const float* a3 = (const float*)d_in[3];
    const float* a4 = (const float*)d_in[4];
    const float* a5 = (const float*)d_in[5];
    float* out = (float*)d_out;

    int total = BATCH * NANCH;
    decode_kernel<<<(total + 255) / 256, 256>>>(p3, p4, p5, a3, a4, a5);
    percls_kernel<<<BATCH * NUM_CLASSES, 256>>>();
    final_kernel<<<BATCH, 256>>>(out);
}

// round 3
// speedup vs baseline: 1.8217x; 1.8217x over previous
#include <cuda_runtime.h>
#include <cstdint>

#define NUM_CLASSES 80
#define PRE_NMS_K   400
#define MAX_BOXES   200
#define NMS_THRESH  0.6f
#define BATCH       8
#define NANCH       16128   // 64*64*3 + 32*32*3 + 16*16*3
#define FLAT_K      (NUM_CLASSES * PRE_NMS_K)   // 32000
#define C5          85
#define NWORD       13      // ceil(400/32)

// ---- device scratch ----
__device__ float g_boxes[BATCH * NANCH * 4];                    // (y1,x1,y2,x2) clipped
__device__ float g_scores[BATCH * NUM_CLASSES * NANCH];         // [b][c][n]
__device__ float g_kept_scores[BATCH * NUM_CLASSES * PRE_NMS_K];
__device__ float g_kept_boxes[BATCH * NUM_CLASSES * PRE_NMS_K * 4];

__device__ __forceinline__ float sigmoidf(float x) {
    return 1.0f / (1.0f + expf(-x));
}

// ============================================================
// Kernel 1: decode. 64 contiguous anchors per block staged in smem.
// Anchors within a tile never cross image/level boundaries
// (12288 and 15360 are multiples of 64).
// ============================================================
__global__ __launch_bounds__(256) void decode_kernel(
    const float* __restrict__ p3, const float* __restrict__ p4, const float* __restrict__ p5,
    const float* __restrict__ a3, const float* __restrict__ a4, const float* __restrict__ a5)
{
    __shared__ float tile[64 * C5];   // stride 85: gcd(85,32)=1 -> conflict-free
    __shared__ float s_obj[64];

    int tid = threadIdx.x;
    int blk = blockIdx.x;
    int b  = blk / (NANCH / 64);
    int n0 = (blk % (NANCH / 64)) * 64;

    const float* p; const float* anc;
    int HW; float stride, sxy; int base;
    if (n0 < 12288)      { p = p3; anc = a3; HW = 64; stride = 8.0f;  sxy = 1.20f; base = 0; }
    else if (n0 < 15360) { p = p4; anc = a4; HW = 32; stride = 16.0f; sxy = 1.10f; base = 12288; }
    else                 { p = p5; anc = a5; HW = 16; stride = 32.0f; sxy = 1.05f; base = 15360; }

    int loc0 = n0 - base;
    const float* src = p + ((size_t)b * HW * HW * 3 + loc0) * C5;

    // fully coalesced cooperative load of 64x85 contiguous floats
    for (int i = tid; i < 64 * C5; i += 256) tile[i] = src[i];
    __syncthreads();

    if (tid < 64) {
        int loc = loc0 + tid;
        int a  = loc % 3;
        int hw = loc / 3;
        int w  = hw % HW;
        int h  = hw / HW;
        const float* r = &tile[tid * C5];

        float invHW = 1.0f / (float)HW;
        float sx = sigmoidf(r[0]);
        float sy = sigmoidf(r[1]);
        float x = (sx * sxy - 0.5f * (sxy - 1.0f) + (float)w) * invHW;
        float y = (sy * sxy - 0.5f * (sxy - 1.0f) + (float)h) * invHW;

        float denom = 1.0f / ((float)HW * stride);
        float bw = expf(r[2]) * anc[a * 2 + 0] * denom;
        float bh = expf(r[3]) * anc[a * 2 + 1] * denom;

        float y1 = fminf(fmaxf(y - 0.5f * bh, 0.0f), 1.0f);
        float x1 = fminf(fmaxf(x - 0.5f * bw, 0.0f), 1.0f);
        float y2 = fminf(fmaxf(y + 0.5f * bh, 0.0f), 1.0f);
        float x2 = fminf(fmaxf(x + 0.5f * bw, 0.0f), 1.0f);

        ((float4*)g_boxes)[(size_t)b * NANCH + n0 + tid] = make_float4(y1, x1, y2, x2);
        s_obj[tid] = sigmoidf(r[4]);
    }
    __syncthreads();

    // scores: warp handles 32 consecutive anchors for a fixed class -> coalesced stores
    size_t sbase = (size_t)b * NUM_CLASSES * NANCH + n0;
    for (int i = tid; i < 64 * NUM_CLASSES; i += 256) {
        int c = i >> 6;
        int a = i & 63;
        float v = sigmoidf(tile[a * C5 + 5 + c]) * s_obj[a];
        g_scores[sbase + (size_t)c * NANCH + a] = v;
    }
}

// ============================================================
// Radix-select over float4 data (all values >= 0). Exact K-th
// largest bit pattern left in *sh_prefix. Warp-aggregated atomics.
// ============================================================
__device__ void radix_kth(const float4* __restrict__ sc4, int n4, int K,
                          unsigned* sh_hist, unsigned* sh_prefix, int* sh_rem)
{
    int tid = threadIdx.x;
    int lane = tid & 31;
    if (tid == 0) { *sh_prefix = 0u; *sh_rem = K; }
    __syncthreads();
    int iters = (n4 + 255) / 256;
    for (int shift = 24; shift >= 0; shift -= 8) {
        sh_hist[tid] = 0u;
        __syncthreads();
        unsigned pref = *sh_prefix;
        for (int it = 0; it < iters; it++) {
            int i = it * 256 + tid;
            bool valid = i < n4;
            float4 v = valid ? sc4[i] : make_float4(0.f, 0.f, 0.f, 0.f);
            unsigned kk[4] = {__float_as_uint(v.x), __float_as_uint(v.y),
                              __float_as_uint(v.z), __float_as_uint(v.w)};
#pragma unroll
            for (int e = 0; e < 4; e++) {
                unsigned k = kk[e];
                bool m = valid && ((shift == 24) || ((k >> (shift + 8)) == pref));
                unsigned bucket = m ? ((k >> shift) & 255u) : 0xFFFFFFFFu;
                unsigned mmask = __match_any_sync(0xFFFFFFFFu, bucket);
                if (m && lane == (__ffs(mmask) - 1))
                    atomicAdd(&sh_hist[bucket], __popc(mmask));
            }
        }
        __syncthreads();
        // warp 0: parallel suffix-scan over 256 buckets (descending)
        if (tid < 32) {
            int hi = 255 - lane * 8;
            unsigned loc[8];
            unsigned s = 0;
#pragma unroll
            for (int e = 0; e < 8; e++) { loc[e] = sh_hist[hi - e]; s += loc[e]; }
            unsigned inc = s;
#pragma unroll
            for (int off = 1; off < 32; off <<= 1) {
                unsigned t2 = __shfl_up_sync(0xFFFFFFFFu, inc, off);
                if (lane >= off) inc += t2;
            }
            unsigned excl = inc - s;
            int rem = *sh_rem;
            bool has = (excl < (unsigned)rem) && ((unsigned)rem <= excl + s);
            unsigned ball = __ballot_sync(0xFFFFFFFFu, has);
            int ldr = (ball == 0u) ? 31 : (__ffs(ball) - 1);  // ball==0 only if rem > total (can't happen with K<=n positives); fall to bucket 0
            if (lane == ldr) {
                unsigned cum = excl;
                int bkt = hi - 7;
#pragma unroll
                for (int e = 0; e < 8; e++) {
                    if (cum + loc[e] >= (unsigned)rem) { bkt = hi - e; break; }
                    cum += loc[e];
                }
                *sh_prefix = (pref << 8) | (unsigned)bkt;
                *sh_rem = rem - (int)cum;
            }
        }
        __syncthreads();
    }
}

// descending bitonic sort of SIZE u64 keys
template <int SIZE>
__device__ void bitonic_desc(unsigned long long* a)
{
    int tid = threadIdx.x;
    for (int k = 2; k <= SIZE; k <<= 1) {
        for (int j = k >> 1; j > 0; j >>= 1) {
            __syncthreads();
            for (int i = tid; i < SIZE; i += 256) {
                int ixj = i ^ j;
                if (ixj > i) {
                    bool seg = (i & k) == 0;
                    unsigned long long x = a[i], y = a[ixj];
                    if (seg ? (x < y) : (x > y)) { a[i] = y; a[ixj] = x; }
                }
            }
        }
    }
    __syncthreads();
}

// warp-aggregated append of (valbits<<32)|(~idx) keys
__device__ __forceinline__ void append_cand(bool take, unsigned k, unsigned idx,
                                            unsigned long long* cand, int cap, int* s_cnt)
{
    unsigned ball = __ballot_sync(0xFFFFFFFFu, take);
    if (ball == 0u) return;
    int lane = threadIdx.x & 31;
    int leader = __ffs(ball) - 1;
    int base;
    if (lane == leader) base = atomicAdd(s_cnt, __popc(ball));
    base = __shfl_sync(0xFFFFFFFFu, base, leader);
    if (take) {
        int pos = base + __popc(ball & ((1u << lane) - 1u));
        if (pos < cap)
            cand[pos] = ((unsigned long long)k << 32) |
                        (unsigned long long)(0xFFFFFFFFu - idx);
    }
}

// ============================================================
// Kernel 2: per (b, class) top-400 + greedy NMS
// ============================================================
__global__ __launch_bounds__(256) void percls_kernel()
{
    __shared__ unsigned hist[256];
    __shared__ unsigned s_prefix;
    __shared__ int s_rem;
    __shared__ unsigned long long cand[1024];
    __shared__ int s_cnt;
    __shared__ float bx0[PRE_NMS_K], bx1[PRE_NMS_K], bx2[PRE_NMS_K], bx3[PRE_NMS_K], ar[PRE_NMS_K];
    __shared__ unsigned mat[PRE_NMS_K][NWORD];
    __shared__ unsigned keepw[NWORD];

    int tid = threadIdx.x;
    int bc = blockIdx.x;
    int b = bc / NUM_CLASSES;
    const float4* sc4 = (const float4*)(g_scores + (size_t)bc * NANCH);
    const int n4 = NANCH / 4;

    radix_kth(sc4, n4, PRE_NMS_K, hist, &s_prefix, &s_rem);
    unsigned T = s_prefix;

    if (tid == 0) s_cnt = 0;
    __syncthreads();
    {
        int iters = (n4 + 255) / 256;
        for (int it = 0; it < iters; it++) {
            int i = it * 256 + tid;
            bool valid = i < n4;
            float4 v = valid ? sc4[i] : make_float4(0.f, 0.f, 0.f, 0.f);
            unsigned kk[4] = {__float_as_uint(v.x), __float_as_uint(v.y),
                              __float_as_uint(v.z), __float_as_uint(v.w)};
#pragma unroll
            for (int e = 0; e < 4; e++)
                append_cand(valid && kk[e] >= T, kk[e], (unsigned)(i * 4 + e), cand, 1024, &s_cnt);
        }
    }
    __syncthreads();
    int cnt = min(s_cnt, 1024);
    if (cnt <= 512) {
        for (int i = tid; i < 512; i += 256) if (i >= cnt) cand[i] = 0ULL;
        bitonic_desc<512>(cand);
    } else {
        for (int i = tid; i < 1024; i += 256) if (i >= cnt) cand[i] = 0ULL;
        bitonic_desc<1024>(cand);
    }

    // gather boxes of sorted top-400
    const float4* gb4 = (const float4*)g_boxes + (size_t)b * NANCH;
    for (int t = tid; t < PRE_NMS_K; t += 256) {
        unsigned idx = 0xFFFFFFFFu - (unsigned)(cand[t] & 0xFFFFFFFFull);
        float4 bp = gb4[idx];
        bx0[t] = bp.x; bx1[t] = bp.y; bx2[t] = bp.z; bx3[t] = bp.w;
        ar[t] = (bp.z - bp.x) * (bp.w - bp.y);
    }
    __syncthreads();

    // suppression bitmask, atomic-free: each thread owns (i, word)
    for (int p = tid; p < PRE_NMS_K * NWORD; p += 256) {
        int i = p % PRE_NMS_K;     // lanes: consecutive i -> conflict-free bx[i]
        int w = p / PRE_NMS_K;     // same word across warp -> bx[j] broadcast
        int jbase = w * 32;
        unsigned bits = 0u;
        if (jbase + 31 > i) {      // word has some j > i
            float iy1 = bx0[i], ix1 = bx1[i], iy2 = bx2[i], ix2 = bx3[i], ia = ar[i];
            int jend = min(32, PRE_NMS_K - jbase);
#pragma unroll 8
            for (int jj = 0; jj < 32; jj++) {
                if (jj >= jend) break;
                int j = jbase + jj;
                if (j > i) {
                    float ty = fmaxf(iy1, bx0[j]);
                    float tx = fmaxf(ix1, bx1[j]);
                    float by = fminf(iy2, bx2[j]);
                    float rx = fminf(ix2, bx3[j]);
                    float hh = fmaxf(by - ty, 0.0f);
                    float ww = fmaxf(rx - tx, 0.0f);
                    float inter = hh * ww;
                    float uni = ia + ar[j] - inter;
                    if (inter > NMS_THRESH * fmaxf(uni, 1e-9f))
                        bits |= (1u << jj);
                }
            }
        }
        mat[i][w] = bits;
    }
    __syncthreads();

    // serial greedy sweep on warp 0
    if (tid < 32) {
        unsigned kw = (tid < 12) ? 0xFFFFFFFFu : ((tid == 12) ? 0xFFFFu : 0u);
        for (int i = 0; i < PRE_NMS_K; i++) {
            unsigned wb = __shfl_sync(0xFFFFFFFFu, kw, i >> 5);
            if ((wb >> (i & 31)) & 1u) {
                if (tid < NWORD) kw &= ~mat[i][tid];
            }
        }
        if (tid < NWORD) keepw[tid] = kw;
    }
    __syncthreads();

    float* ks = g_kept_scores + (size_t)bc * PRE_NMS_K;
    float4* kb4 = (float4*)(g_kept_boxes + (size_t)bc * PRE_NMS_K * 4);
    for (int t = tid; t < PRE_NMS_K; t += 256) {
        float v = __uint_as_float((unsigned)(cand[t] >> 32));
        int kept = (keepw[t >> 5] >> (t & 31)) & 1;
        ks[t] = (kept && v > 0.0f) ? v : 0.0f;
        kb4[t] = make_float4(bx0[t], bx1[t], bx2[t], bx3[t]);
    }
}

// ============================================================
// Kernel 3: per-image top-200
// out layout (float32): bbox[8][200][4] | conf[8][200] | cls[8][200] | num[8]
// ============================================================
__global__ __launch_bounds__(256) void final_kernel(float* __restrict__ out)
{
    __shared__ unsigned hist[256];
    __shared__ unsigned s_prefix;
    __shared__ int s_rem;
    __shared__ unsigned long long cand[512];
    __shared__ int s_cnt, s_nval;

    int tid = threadIdx.x;
    int b = blockIdx.x;
    const float4* sc4 = (const float4*)(g_kept_scores + (size_t)b * FLAT_K);
    const int n4 = FLAT_K / 4;

    radix_kth(sc4, n4, MAX_BOXES, hist, &s_prefix, &s_rem);
    unsigned T = s_prefix;

    if (tid == 0) { s_cnt = 0; s_nval = 0; }
    __syncthreads();
    {
        int iters = (n4 + 255) / 256;
        for (int it = 0; it < iters; it++) {
            int i = it * 256 + tid;
            bool valid = i < n4;
            float4 v = valid ? sc4[i] : make_float4(0.f, 0.f, 0.f, 0.f);
            unsigned kk[4] = {__float_as_uint(v.x), __float_as_uint(v.y),
                              __float_as_uint(v.z), __float_as_uint(v.w)};
#pragma unroll
            for (int e = 0; e < 4; e++) {
                bool take = valid && ((T > 0u) ? (kk[e] >= T) : (kk[e] > 0u));
                append_cand(take, kk[e], (unsigned)(i * 4 + e), cand, 512, &s_cnt);
            }
        }
    }
    __syncthreads();
    int cnt = min(s_cnt, 512);
    for (int i = tid; i < 512; i += 256)
        if (i >= cnt) cand[i] = 0ULL;
    bitonic_desc<512>(cand);

    const float4* kb4 = (const float4*)(g_kept_boxes + (size_t)b * FLAT_K * 4);
    for (int t = tid; t < MAX_BOXES; t += 256) {
        unsigned long long e = cand[t];
        float v = __uint_as_float((unsigned)(e >> 32));
        bool valid = v > 0.0f;
        unsigned flat = 0xFFFFFFFFu - (unsigned)(e & 0xFFFFFFFFull);
        float4 bb = make_float4(0.f, 0.f, 0.f, 0.f);
        float clsf = 0.f;
        if (valid) {
            bb = kb4[flat];
            clsf = (float)(flat / PRE_NMS_K);
            atomicAdd(&s_nval, 1);
        }
        int o = b * MAX_BOXES + t;
        ((float4*)out)[o] = bb;
        out[BATCH * MAX_BOXES * 4 + o] = v;
        out[BATCH * MAX_BOXES * 4 + BATCH * MAX_BOXES + o] = clsf;
    }
    __syncthreads();
    if (tid == 0)
        out[BATCH * MAX_BOXES * 4 + 2 * BATCH * MAX_BOXES + b] = (float)s_nval;
}

// ============================================================
extern "C" void kernel_launch(void* const* d_in, const int* in_sizes, int n_in,
                              void* d_out, int out_size)
{
    const float* p3 = (const float*)d_in[0];
    const float* p4 = (const float*)d_in[1];
    const float* p5 = (const float*)d_in[2];
    const float* a3 = (const float*)d_in[3];
    const float* a4 = (const float*)d_in[4];
    const float* a5 = (const float*)d_in[5];
    float* out = (float*)d_out;

    decode_kernel<<<BATCH * (NANCH / 64), 256>>>(p3, p4, p5, a3, a4, a5);
    percls_kernel<<<BATCH * NUM_CLASSES, 256>>>();
    final_kernel<<<BATCH, 256>>>(out);
}

// round 4
// speedup vs baseline: 2.2814x; 1.2523x over previous
#include <cuda_runtime.h>
#include <cstdint>

#define NUM_CLASSES 80
#define PRE_NMS_K   400
#define MAX_BOXES   200
#define NMS_THRESH  0.6f
#define BATCH       8
#define NANCH       16128   // 64*64*3 + 32*32*3 + 16*16*3
#define FLAT_K      (NUM_CLASSES * PRE_NMS_K)   // 32000
#define C5          85
#define NWORD       13      // ceil(400/32)

// ---- device scratch ----
__device__ float g_boxes[BATCH * NANCH * 4];                    // (y1,x1,y2,x2) clipped
__device__ float g_scores[BATCH * NUM_CLASSES * NANCH];         // [b][c][n]
__device__ float g_kept_scores[BATCH * NUM_CLASSES * PRE_NMS_K];
__device__ unsigned g_kept_idx[BATCH * NUM_CLASSES * PRE_NMS_K];

__device__ __forceinline__ float sigmoidf(float x) {
    return 1.0f / (1.0f + expf(-x));
}

// ============================================================
// Kernel 1: decode. 64 contiguous anchors per block staged in smem.
// ============================================================
__global__ __launch_bounds__(256) void decode_kernel(
    const float* __restrict__ p3, const float* __restrict__ p4, const float* __restrict__ p5,
    const float* __restrict__ a3, const float* __restrict__ a4, const float* __restrict__ a5)
{
    __shared__ float tile[64 * C5];   // stride 85: gcd(85,32)=1 -> conflict-free
    __shared__ float s_obj[64];

    int tid = threadIdx.x;
    int blk = blockIdx.x;
    int b  = blk / (NANCH / 64);
    int n0 = (blk % (NANCH / 64)) * 64;

    const float* p; const float* anc;
    int HW; float stride, sxy; int base;
    if (n0 < 12288)      { p = p3; anc = a3; HW = 64; stride = 8.0f;  sxy = 1.20f; base = 0; }
    else if (n0 < 15360) { p = p4; anc = a4; HW = 32; stride = 16.0f; sxy = 1.10f; base = 12288; }
    else                 { p = p5; anc = a5; HW = 16; stride = 32.0f; sxy = 1.05f; base = 15360; }

    int loc0 = n0 - base;
    const float* src = p + ((size_t)b * HW * HW * 3 + loc0) * C5;

    for (int i = tid; i < 64 * C5; i += 256) tile[i] = src[i];
    __syncthreads();

    if (tid < 64) {
        int loc = loc0 + tid;
        int a  = loc % 3;
        int hw = loc / 3;
        int w  = hw % HW;
        int h  = hw / HW;
        const float* r = &tile[tid * C5];

        float invHW = 1.0f / (float)HW;
        float sx = sigmoidf(r[0]);
        float sy = sigmoidf(r[1]);
        float x = (sx * sxy - 0.5f * (sxy - 1.0f) + (float)w) * invHW;
        float y = (sy * sxy - 0.5f * (sxy - 1.0f) + (float)h) * invHW;

        float denom = 1.0f / ((float)HW * stride);
        float bw = expf(r[2]) * anc[a * 2 + 0] * denom;
        float bh = expf(r[3]) * anc[a * 2 + 1] * denom;

        float y1 = fminf(fmaxf(y - 0.5f * bh, 0.0f), 1.0f);
        float x1 = fminf(fmaxf(x - 0.5f * bw, 0.0f), 1.0f);
        float y2 = fminf(fmaxf(y + 0.5f * bh, 0.0f), 1.0f);
        float x2 = fminf(fmaxf(x + 0.5f * bw, 0.0f), 1.0f);

        ((float4*)g_boxes)[(size_t)b * NANCH + n0 + tid] = make_float4(y1, x1, y2, x2);
        s_obj[tid] = sigmoidf(r[4]);
    }
    __syncthreads();

    size_t sbase = (size_t)b * NUM_CLASSES * NANCH + n0;
    for (int i = tid; i < 64 * NUM_CLASSES; i += 256) {
        int c = i >> 6;
        int a = i & 63;
        float v = sigmoidf(tile[a * C5 + 5 + c]) * s_obj[a];
        g_scores[sbase + (size_t)c * NANCH + a] = v;
    }
}

// ============================================================
// Adaptive radix threshold: returns T such that
//   count(key >= T) >= K, and (unless forced to the exact level)
//   count(key >= T) <= cap.
// Early-exits as soon as the chosen bucket fits within cap.
// ============================================================
struct RadixState {
    unsigned prefix, T;
    int rem, base, done;
};

__device__ unsigned radix_thresh(const float4* __restrict__ sc4, int n4, int K, int cap,
                                 unsigned* sh_hist, RadixState* st)
{
    int tid = threadIdx.x;
    int lane = tid & 31;
    if (tid == 0) { st->prefix = 0u; st->rem = K; st->base = 0; st->done = 0; }
    __syncthreads();
    int iters = (n4 + 255) / 256;
    for (int shift = 24; shift >= 0; shift -= 8) {
        sh_hist[tid] = 0u;
        __syncthreads();
        unsigned pref = st->prefix;
        for (int it = 0; it < iters; it++) {
            int i = it * 256 + tid;
            bool valid = i < n4;
            float4 v = valid ? sc4[i] : make_float4(0.f, 0.f, 0.f, 0.f);
            unsigned kk[4] = {__float_as_uint(v.x), __float_as_uint(v.y),
                              __float_as_uint(v.z), __float_as_uint(v.w)};
#pragma unroll
            for (int e = 0; e < 4; e++) {
                unsigned k = kk[e];
                bool m = valid && ((shift == 24) || ((k >> (shift + 8)) == pref));
                unsigned bucket = m ? ((k >> shift) & 255u) : 0xFFFFFFFFu;
                unsigned mmask = __match_any_sync(0xFFFFFFFFu, bucket);
                if (m && lane == (__ffs(mmask) - 1))
                    atomicAdd(&sh_hist[bucket], __popc(mmask));
            }
        }
        __syncthreads();
        // warp 0: descending suffix-scan over 256 buckets, pick bucket of rank rem
        if (tid < 32) {
            int hi = 255 - lane * 8;
            unsigned loc[8];
            unsigned s = 0;
#pragma unroll
            for (int e = 0; e < 8; e++) { loc[e] = sh_hist[hi - e]; s += loc[e]; }
            unsigned inc = s;
#pragma unroll
            for (int off = 1; off < 32; off <<= 1) {
                unsigned t2 = __shfl_up_sync(0xFFFFFFFFu, inc, off);
                if (lane >= off) inc += t2;
            }
            unsigned excl = inc - s;
            int rem = st->rem;
            bool has = (excl < (unsigned)rem) && ((unsigned)rem <= excl + s);
            unsigned ball = __ballot_sync(0xFFFFFFFFu, has);
            int ldr = (ball == 0u) ? 31 : (__ffs(ball) - 1);
            if (lane == ldr) {
                unsigned cum = excl;
                int bkt = hi - 7;
                unsigned bcount = loc[7];
#pragma unroll
                for (int e = 0; e < 8; e++) {
                    if (cum + loc[e] >= (unsigned)rem) { bkt = hi - e; bcount = loc[e]; break; }
                    cum += loc[e];
                }
                int tot = st->base + (int)cum + (int)bcount;   // count(>= bucket floor)
                if (tot <= cap || shift == 0) {
                    st->T = (((pref << 8) | (unsigned)bkt) << shift);
                    st->done = 1;
                } else {
                    st->prefix = (pref << 8) | (unsigned)bkt;
                    st->rem = rem - (int)cum;
                    st->base = st->base + (int)cum;
                }
            }
        }
        __syncthreads();
        if (st->done) break;
    }
    return st->T;
}

// descending bitonic sort of SIZE u64 keys
template <int SIZE>
__device__ void bitonic_desc(unsigned long long* a)
{
    int tid = threadIdx.x;
    for (int k = 2; k <= SIZE; k <<= 1) {
        for (int j = k >> 1; j > 0; j >>= 1) {
            __syncthreads();
            for (int i = tid; i < SIZE; i += 256) {
                int ixj = i ^ j;
                if (ixj > i) {
                    bool seg = (i & k) == 0;
                    unsigned long long x = a[i], y = a[ixj];
                    if (seg ? (x < y) : (x > y)) { a[i] = y; a[ixj] = x; }
                }
            }
        }
    }
    __syncthreads();
}

// warp-aggregated append of (valbits<<32)|(~idx) keys
__device__ __forceinline__ void append_cand(bool take, unsigned k, unsigned idx,
                                            unsigned long long* cand, int cap, int* s_cnt)
{
    unsigned ball = __ballot_sync(0xFFFFFFFFu, take);
    if (ball == 0u) return;
    int lane = threadIdx.x & 31;
    int leader = __ffs(ball) - 1;
    int base;
    if (lane == leader) base = atomicAdd(s_cnt, __popc(ball));
    base = __shfl_sync(0xFFFFFFFFu, base, leader);
    if (take) {
        int pos = base + __popc(ball & ((1u << lane) - 1u));
        if (pos < cap)
            cand[pos] = ((unsigned long long)k << 32) |
                        (unsigned long long)(0xFFFFFFFFu - idx);
    }
}

// ============================================================
// Kernel 2: per (b, class) top-400 + greedy NMS
// ============================================================
__global__ __launch_bounds__(256) void percls_kernel()
{
    __shared__ unsigned hist[256];
    __shared__ RadixState rst;
    __shared__ unsigned long long cand[1024];
    __shared__ int s_cnt;
    __shared__ float bx0[PRE_NMS_K], bx1[PRE_NMS_K], bx2[PRE_NMS_K], bx3[PRE_NMS_K], ar[PRE_NMS_K];
    __shared__ unsigned mat[PRE_NMS_K][NWORD];
    __shared__ unsigned nzmask[NWORD];
    __shared__ unsigned keepw[NWORD];

    int tid = threadIdx.x;
    int bc = blockIdx.x;
    int b = bc / NUM_CLASSES;
    const float4* sc4 = (const float4*)(g_scores + (size_t)bc * NANCH);
    const int n4 = NANCH / 4;

    unsigned T = radix_thresh(sc4, n4, PRE_NMS_K, 1024, hist, &rst);

    if (tid == 0) s_cnt = 0;
    if (tid < NWORD) nzmask[tid] = 0u;
    __syncthreads();
    {
        int iters = (n4 + 255) / 256;
        for (int it = 0; it < iters; it++) {
            int i = it * 256 + tid;
            bool valid = i < n4;
            float4 v = valid ? sc4[i] : make_float4(0.f, 0.f, 0.f, 0.f);
            unsigned kk[4] = {__float_as_uint(v.x), __float_as_uint(v.y),
                              __float_as_uint(v.z), __float_as_uint(v.w)};
#pragma unroll
            for (int e = 0; e < 4; e++)
                append_cand(valid && kk[e] >= T, kk[e], (unsigned)(i * 4 + e), cand, 1024, &s_cnt);
        }
    }
    __syncthreads();
    int cnt = min(s_cnt, 1024);
    if (cnt <= 512) {
        for (int i = tid; i < 512; i += 256) if (i >= cnt) cand[i] = 0ULL;
        bitonic_desc<512>(cand);
    } else {
        for (int i = tid; i < 1024; i += 256) if (i >= cnt) cand[i] = 0ULL;
        bitonic_desc<1024>(cand);
    }

    // gather boxes of sorted top-400
    const float4* gb4 = (const float4*)g_boxes + (size_t)b * NANCH;
    for (int t = tid; t < PRE_NMS_K; t += 256) {
        unsigned idx = 0xFFFFFFFFu - (unsigned)(cand[t] & 0xFFFFFFFFull);
        float4 bp = gb4[idx];
        bx0[t] = bp.x; bx1[t] = bp.y; bx2[t] = bp.z; bx3[t] = bp.w;
        ar[t] = (bp.z - bp.x) * (bp.w - bp.y);
    }
    __syncthreads();

    // suppression bitmask, atomic-free, 2-row register tiling:
    // thread owns rows (2*i2, 2*i2+1) x word w; j-box loads shared between rows.
    for (int p = tid; p < (PRE_NMS_K / 2) * NWORD; p += 256) {
        int i2 = p % (PRE_NMS_K / 2);
        int w  = p / (PRE_NMS_K / 2);
        int i0 = i2 * 2;
        int i1 = i0 + 1;
        int jbase = w * 32;
        unsigned bits0 = 0u, bits1 = 0u;
        if (jbase + 31 > i0) {
            float a_y1 = bx0[i0], a_x1 = bx1[i0], a_y2 = bx2[i0], a_x2 = bx3[i0], a_ar = ar[i0];
            float c_y1 = bx0[i1], c_x1 = bx1[i1], c_y2 = bx2[i1], c_x2 = bx3[i1], c_ar = ar[i1];
            int jend = min(32, PRE_NMS_K - jbase);
            for (int jj = 0; jj < jend; jj++) {
                int j = jbase + jj;
                float jy1 = bx0[j], jx1 = bx1[j], jy2 = bx2[j], jx2 = bx3[j], jar = ar[j];
                if (j > i0) {
                    float hh = fmaxf(fminf(a_y2, jy2) - fmaxf(a_y1, jy1), 0.0f);
                    float ww = fmaxf(fminf(a_x2, jx2) - fmaxf(a_x1, jx1), 0.0f);
                    float inter = hh * ww;
                    float uni = a_ar + jar - inter;
                    if (inter > NMS_THRESH * fmaxf(uni, 1e-9f)) bits0 |= (1u << jj);
                }
                if (j > i1) {
                    float hh = fmaxf(fminf(c_y2, jy2) - fmaxf(c_y1, jy1), 0.0f);
                    float ww = fmaxf(fminf(c_x2, jx2) - fmaxf(c_x1, jx1), 0.0f);
                    float inter = hh * ww;
                    float uni = c_ar + jar - inter;
                    if (inter > NMS_THRESH * fmaxf(uni, 1e-9f)) bits1 |= (1u << jj);
                }
            }
        }
        mat[i0][w] = bits0;
        mat[i1][w] = bits1;
        if (bits0) atomicOr(&nzmask[i0 >> 5], 1u << (i0 & 31));
        if (bits1) atomicOr(&nzmask[i1 >> 5], 1u << (i1 & 31));
    }
    __syncthreads();

    // sparse greedy sweep on warp 0: only rows that actually suppress matter
    if (tid < 32) {
        unsigned kw = (tid < 12) ? 0xFFFFFFFFu : ((tid == 12) ? 0xFFFFu : 0u);
        for (int iw = 0; iw < NWORD; iw++) {
            unsigned done = 0u;
            while (true) {
                unsigned wb = __shfl_sync(0xFFFFFFFFu, kw, iw);
                unsigned act = wb & nzmask[iw] & ~done;
                if (act == 0u) break;
                int bit = __ffs(act) - 1;
                done |= (1u << bit);
                int i = iw * 32 + bit;
                if (tid < NWORD) kw &= ~mat[i][tid];
            }
        }
        if (tid < NWORD) keepw[tid] = kw;
    }
    __syncthreads();

    float* ks = g_kept_scores + (size_t)bc * PRE_NMS_K;
    unsigned* ki = g_kept_idx + (size_t)bc * PRE_NMS_K;
    for (int t = tid; t < PRE_NMS_K; t += 256) {
        float v = __uint_as_float((unsigned)(cand[t] >> 32));
        int kept = (keepw[t >> 5] >> (t & 31)) & 1;
        ks[t] = (kept && v > 0.0f) ? v : 0.0f;
        ki[t] = 0xFFFFFFFFu - (unsigned)(cand[t] & 0xFFFFFFFFull);
    }
}

// ============================================================
// Kernel 3: per-image top-200
// out layout (float32): bbox[8][200][4] | conf[8][200] | cls[8][200] | num[8]
// ============================================================
__global__ __launch_bounds__(256) void final_kernel(float* __restrict__ out)
{
    __shared__ unsigned hist[256];
    __shared__ RadixState rst;
    __shared__ unsigned long long cand[512];
    __shared__ int s_cnt, s_nval;

    int tid = threadIdx.x;
    int b = blockIdx.x;
    const float4* sc4 = (const float4*)(g_kept_scores + (size_t)b * FLAT_K);
    const int n4 = FLAT_K / 4;

    unsigned T = radix_thresh(sc4, n4, MAX_BOXES, 512, hist, &rst);

    if (tid == 0) { s_cnt = 0; s_nval = 0; }
    __syncthreads();
    {
        int iters = (n4 + 255) / 256;
        for (int it = 0; it < iters; it++) {
            int i = it * 256 + tid;
            bool valid = i < n4;
            float4 v = valid ? sc4[i] : make_float4(0.f, 0.f, 0.f, 0.f);
            unsigned kk[4] = {__float_as_uint(v.x), __float_as_uint(v.y),
                              __float_as_uint(v.z), __float_as_uint(v.w)};
#pragma unroll
            for (int e = 0; e < 4; e++) {
                bool take = valid && ((T > 0u) ? (kk[e] >= T) : (kk[e] > 0u));
                append_cand(take, kk[e], (unsigned)(i * 4 + e), cand, 512, &s_cnt);
            }
        }
    }
    __syncthreads();
    int cnt = min(s_cnt, 512);
    for (int i = tid; i < 512; i += 256)
        if (i >= cnt) cand[i] = 0ULL;
    bitonic_desc<512>(cand);

    const unsigned* ki = g_kept_idx + (size_t)b * FLAT_K;
    const float4* gb4 = (const float4*)g_boxes + (size_t)b * NANCH;
    for (int t = tid; t < MAX_BOXES; t += 256) {
        unsigned long long e = cand[t];
        float v = __uint_as_float((unsigned)(e >> 32));
        bool valid = v > 0.0f;
        unsigned flat = 0xFFFFFFFFu - (unsigned)(e & 0xFFFFFFFFull);
        float4 bb = make_float4(0.f, 0.f, 0.f, 0.f);
        float clsf = 0.f;
        if (valid) {
            bb = gb4[ki[flat]];
            clsf = (float)(flat / PRE_NMS_K);
            atomicAdd(&s_nval, 1);
        }
        int o = b * MAX_BOXES + t;
        ((float4*)out)[o] = bb;
        out[BATCH * MAX_BOXES * 4 + o] = v;
        out[BATCH * MAX_BOXES * 4 + BATCH * MAX_BOXES + o] = clsf;
    }
    __syncthreads();
    if (tid == 0)
        out[BATCH * MAX_BOXES * 4 + 2 * BATCH * MAX_BOXES + b] = (float)s_nval;
}

// ============================================================
extern "C" void kernel_launch(void* const* d_in, const int* in_sizes, int n_in,
                              void* d_out, int out_size)
{
    const float* p3 = (const float*)d_in[0];
    const float* p4 = (const float*)d_in[1];
    const float* p5 = (const float*)d_in[2];
    const float* a3 = (const float*)d_in[3];
    const float* a4 = (const float*)d_in[4];
    const float* a5 = (const float*)d_in[5];
    float* out = (float*)d_out;

    decode_kernel<<<BATCH * (NANCH / 64), 256>>>(p3, p4, p5, a3, a4, a5);
    percls_kernel<<<BATCH * NUM_CLASSES, 256>>>();
    final_kernel<<<BATCH, 256>>>(out);
}

// round 5
// speedup vs baseline: 2.2944x; 1.0057x over previous
#include <cuda_runtime.h>
#include <cstdint>

#define NUM_CLASSES 80
#define PRE_NMS_K   400
#define MAX_BOXES   200
#define NMS_THRESH  0.6f
#define BATCH       8
#define NANCH       16128   // 64*64*3 + 32*32*3 + 16*16*3
#define FLAT_K      (NUM_CLASSES * PRE_NMS_K)   // 32000
#define C5          85
#define NWORD       13      // ceil(400/32)

// ---- device scratch ----
__device__ float g_boxes[BATCH * NANCH * 4];                    // (y1,x1,y2,x2) clipped
__device__ float g_scores[BATCH * NUM_CLASSES * NANCH];         // [b][c][n]
__device__ float g_kept_scores[BATCH * NUM_CLASSES * PRE_NMS_K];
__device__ unsigned g_kept_idx[BATCH * NUM_CLASSES * PRE_NMS_K];

__device__ __forceinline__ float sigmoidf(float x) {
    return 1.0f / (1.0f + expf(-x));
}

// ============================================================
// Kernel 1: decode. 64 contiguous anchors per block, float4 I/O.
// ============================================================
__global__ __launch_bounds__(256) void decode_kernel(
    const float* __restrict__ p3, const float* __restrict__ p4, const float* __restrict__ p5,
    const float* __restrict__ a3, const float* __restrict__ a4, const float* __restrict__ a5)
{
    __shared__ float4 tile4[64 * C5 / 4];   // 1360 float4 = 64x85 floats (contiguous)
    __shared__ float s_obj[64];
    float* tile = (float*)tile4;

    int tid = threadIdx.x;
    int blk = blockIdx.x;
    int b  = blk / (NANCH / 64);
    int n0 = (blk % (NANCH / 64)) * 64;

    const float* p; const float* anc;
    int HW; float stride, sxy; int base;
    if (n0 < 12288)      { p = p3; anc = a3; HW = 64; stride = 8.0f;  sxy = 1.20f; base = 0; }
    else if (n0 < 15360) { p = p4; anc = a4; HW = 32; stride = 16.0f; sxy = 1.10f; base = 12288; }
    else                 { p = p5; anc = a5; HW = 16; stride = 32.0f; sxy = 1.05f; base = 15360; }

    int loc0 = n0 - base;
    const float4* src4 = (const float4*)(p + ((size_t)b * HW * HW * 3 + loc0) * C5);

    for (int i = tid; i < 64 * C5 / 4; i += 256) tile4[i] = src4[i];
    __syncthreads();

    if (tid < 64) {
        int loc = loc0 + tid;
        int a  = loc % 3;
        int hw = loc / 3;
        int w  = hw % HW;
        int h  = hw / HW;
        const float* r = &tile[tid * C5];

        float invHW = 1.0f / (float)HW;
        float sx = sigmoidf(r[0]);
        float sy = sigmoidf(r[1]);
        float x = (sx * sxy - 0.5f * (sxy - 1.0f) + (float)w) * invHW;
        float y = (sy * sxy - 0.5f * (sxy - 1.0f) + (float)h) * invHW;

        float denom = 1.0f / ((float)HW * stride);
        float bw = expf(r[2]) * anc[a * 2 + 0] * denom;
        float bh = expf(r[3]) * anc[a * 2 + 1] * denom;

        float y1 = fminf(fmaxf(y - 0.5f * bh, 0.0f), 1.0f);
        float x1 = fminf(fmaxf(x - 0.5f * bw, 0.0f), 1.0f);
        float y2 = fminf(fmaxf(y + 0.5f * bh, 0.0f), 1.0f);
        float x2 = fminf(fmaxf(x + 0.5f * bw, 0.0f), 1.0f);

        ((float4*)g_boxes)[(size_t)b * NANCH + n0 + tid] = make_float4(y1, x1, y2, x2);
        s_obj[tid] = sigmoidf(r[4]);
    }
    __syncthreads();

    // scores: one float4 store = 4 consecutive anchors, fixed class
    size_t sbase = (size_t)b * NUM_CLASSES * NANCH + n0;
    for (int i = tid; i < 64 * NUM_CLASSES / 4; i += 256) {
        int c  = i >> 4;            // class
        int a0 = (i & 15) * 4;      // anchor base
        float4 v;
        v.x = sigmoidf(tile[(a0 + 0) * C5 + 5 + c]) * s_obj[a0 + 0];
        v.y = sigmoidf(tile[(a0 + 1) * C5 + 5 + c]) * s_obj[a0 + 1];
        v.z = sigmoidf(tile[(a0 + 2) * C5 + 5 + c]) * s_obj[a0 + 2];
        v.w = sigmoidf(tile[(a0 + 3) * C5 + 5 + c]) * s_obj[a0 + 3];
        *(float4*)(g_scores + sbase + (size_t)c * NANCH + a0) = v;
    }
}

// ============================================================
// Adaptive radix threshold with fine first pass.
// Level 0: 2048 bins on bits[30:20] (values positive -> k>>20 < 2048).
// Levels 1,2: 1024 bins on bits[19:10], [9:0] (rare fallback).
// Returns T with count(>=T) >= K and (unless exact level) <= cap.
// ============================================================
struct RadixState { unsigned prefix, T; int rem, done; };

__device__ unsigned radix_thresh(const float4* __restrict__ sc4, int n4, int K, int cap,
                                 unsigned* hist /*2048*/, RadixState* st)
{
    int tid = threadIdx.x;
    int lane = tid & 31;
    if (tid == 0) { st->prefix = 0u; st->rem = K; st->done = 0; }
    int iters = (n4 + 255) / 256;

    for (int lvl = 0; lvl < 3; lvl++) {
        const int shift = (lvl == 0) ? 20 : ((lvl == 1) ? 10 : 0);
        const int bins  = (lvl == 0) ? 2048 : 1024;
        for (int i = tid; i < bins; i += 256) hist[i] = 0u;
        __syncthreads();
        unsigned pref = st->prefix;
        for (int it = 0; it < iters; it++) {
            int i = it * 256 + tid;
            if (i < n4) {
                float4 v = sc4[i];
                unsigned kk[4] = {__float_as_uint(v.x), __float_as_uint(v.y),
                                  __float_as_uint(v.z), __float_as_uint(v.w)};
#pragma unroll
                for (int e = 0; e < 4; e++) {
                    unsigned k = kk[e];
                    if (lvl == 0 || (k >> (shift + 10)) == pref)
                        atomicAdd(&hist[(k >> shift) & (bins - 1)], 1u);
                }
            }
        }
        __syncthreads();
        // warp 0: descending suffix scan, pick bucket of rank rem
        if (tid < 32) {
            int per = bins / 32;              // 64 or 32
            int hi = bins - 1 - lane * per;
            unsigned s = 0;
            for (int e = 0; e < per; e++) s += hist[hi - e];
            unsigned inc = s;
#pragma unroll
            for (int off = 1; off < 32; off <<= 1) {
                unsigned t2 = __shfl_up_sync(0xFFFFFFFFu, inc, off);
                if (lane >= off) inc += t2;
            }
            unsigned excl = inc - s;
            int rem = st->rem;
            bool has = (excl < (unsigned)rem) && ((unsigned)rem <= inc);
            unsigned ball = __ballot_sync(0xFFFFFFFFu, has);
            int ldr = (ball == 0u) ? 31 : (__ffs(ball) - 1);
            if (lane == ldr) {
                unsigned cum = excl;
                int bkt = hi - per + 1;
                unsigned bcount = 0u;
                for (int e = 0; e < per; e++) {
                    unsigned h = hist[hi - e];
                    if (cum + h >= (unsigned)rem) { bkt = hi - e; bcount = h; break; }
                    cum += h;
                }
                unsigned newpref = (lvl == 0) ? (unsigned)bkt
                                              : ((pref << 10) | (unsigned)bkt);
                int tot = (K - rem) + (int)cum + (int)bcount;   // count(>= bucket floor)
                if (tot <= cap || lvl == 2) {
                    st->T = newpref << shift;
                    st->done = 1;
                } else {
                    st->prefix = newpref;
                    st->rem = rem - (int)cum;
                }
            }
        }
        __syncthreads();
        if (st->done) break;
    }
    return st->T;
}

// descending bitonic sort of SIZE u64 keys
template <int SIZE>
__device__ void bitonic_desc(unsigned long long* a)
{
    int tid = threadIdx.x;
    for (int k = 2; k <= SIZE; k <<= 1) {
        for (int j = k >> 1; j > 0; j >>= 1) {
            __syncthreads();
            for (int i = tid; i < SIZE; i += 256) {
                int ixj = i ^ j;
                if (ixj > i) {
                    bool seg = (i & k) == 0;
                    unsigned long long x = a[i], y = a[ixj];
                    if (seg ? (x < y) : (x > y)) { a[i] = y; a[ixj] = x; }
                }
            }
        }
    }
    __syncthreads();
}

// warp-aggregated append of (valbits<<32)|(~idx) keys
__device__ __forceinline__ void append_cand(bool take, unsigned k, unsigned idx,
                                            unsigned long long* cand, int cap, int* s_cnt)
{
    unsigned ball = __ballot_sync(0xFFFFFFFFu, take);
    if (ball == 0u) return;
    int lane = threadIdx.x & 31;
    int leader = __ffs(ball) - 1;
    int base;
    if (lane == leader) base = atomicAdd(s_cnt, __popc(ball));
    base = __shfl_sync(0xFFFFFFFFu, base, leader);
    if (take) {
        int pos = base + __popc(ball & ((1u << lane) - 1u));
        if (pos < cap)
            cand[pos] = ((unsigned long long)k << 32) |
                        (unsigned long long)(0xFFFFFFFFu - idx);
    }
}

// ============================================================
// Kernel 2: per (b, class) top-400 + greedy NMS
// ============================================================
__global__ __launch_bounds__(256) void percls_kernel()
{
    __shared__ union {
        unsigned hist[2048];                 // radix phase
        unsigned mat[PRE_NMS_K][NWORD];      // NMS phase (larger)
    } u;
    __shared__ RadixState rst;
    __shared__ unsigned long long cand[1024];
    __shared__ int s_cnt;
    __shared__ float bx0[PRE_NMS_K], bx1[PRE_NMS_K], bx2[PRE_NMS_K], bx3[PRE_NMS_K], ar[PRE_NMS_K];
    __shared__ unsigned nzmask[NWORD];
    __shared__ unsigned keepw[NWORD];

    int tid = threadIdx.x;
    int bc = blockIdx.x;
    int b = bc / NUM_CLASSES;
    const float4* sc4 = (const float4*)(g_scores + (size_t)bc * NANCH);
    const int n4 = NANCH / 4;

    unsigned T = radix_thresh(sc4, n4, PRE_NMS_K, 1024, u.hist, &rst);

    if (tid == 0) s_cnt = 0;
    if (tid < NWORD) nzmask[tid] = 0u;
    __syncthreads();
    {
        int iters = (n4 + 255) / 256;
        for (int it = 0; it < iters; it++) {
            int i = it * 256 + tid;
            bool valid = i < n4;
            float4 v = valid ? sc4[i] : make_float4(0.f, 0.f, 0.f, 0.f);
            unsigned kk[4] = {__float_as_uint(v.x), __float_as_uint(v.y),
                              __float_as_uint(v.z), __float_as_uint(v.w)};
#pragma unroll
            for (int e = 0; e < 4; e++)
                append_cand(valid && kk[e] >= T, kk[e], (unsigned)(i * 4 + e), cand, 1024, &s_cnt);
        }
    }
    __syncthreads();
    int cnt = min(s_cnt, 1024);
    if (cnt <= 512) {
        for (int i = tid; i < 512; i += 256) if (i >= cnt) cand[i] = 0ULL;
        bitonic_desc<512>(cand);
    } else {
        for (int i = tid; i < 1024; i += 256) if (i >= cnt) cand[i] = 0ULL;
        bitonic_desc<1024>(cand);
    }

    // gather boxes of sorted top-400
    const float4* gb4 = (const float4*)g_boxes + (size_t)b * NANCH;
    for (int t = tid; t < PRE_NMS_K; t += 256) {
        unsigned idx = 0xFFFFFFFFu - (unsigned)(cand[t] & 0xFFFFFFFFull);
        float4 bp = gb4[idx];
        bx0[t] = bp.x; bx1[t] = bp.y; bx2[t] = bp.z; bx3[t] = bp.w;
        ar[t] = (bp.z - bp.x) * (bp.w - bp.y);
    }
    __syncthreads();

    // suppression bitmask, atomic-free, 2-row register tiling
    for (int p = tid; p < (PRE_NMS_K / 2) * NWORD; p += 256) {
        int i2 = p % (PRE_NMS_K / 2);
        int w  = p / (PRE_NMS_K / 2);
        int i0 = i2 * 2;
        int i1 = i0 + 1;
        int jbase = w * 32;
        unsigned bits0 = 0u, bits1 = 0u;
        if (jbase + 31 > i0) {
            float a_y1 = bx0[i0], a_x1 = bx1[i0], a_y2 = bx2[i0], a_x2 = bx3[i0], a_ar = ar[i0];
            float c_y1 = bx0[i1], c_x1 = bx1[i1], c_y2 = bx2[i1], c_x2 = bx3[i1], c_ar = ar[i1];
            int jend = min(32, PRE_NMS_K - jbase);
            for (int jj = 0; jj < jend; jj++) {
                int j = jbase + jj;
                float jy1 = bx0[j], jx1 = bx1[j], jy2 = bx2[j], jx2 = bx3[j], jar = ar[j];
                if (j > i0) {
                    float hh = fmaxf(fminf(a_y2, jy2) - fmaxf(a_y1, jy1), 0.0f);
                    float ww = fmaxf(fminf(a_x2, jx2) - fmaxf(a_x1, jx1), 0.0f);
                    float inter = hh * ww;
                    float uni = a_ar + jar - inter;
                    if (inter > NMS_THRESH * fmaxf(uni, 1e-9f)) bits0 |= (1u << jj);
                }
                if (j > i1) {
                    float hh = fmaxf(fminf(c_y2, jy2) - fmaxf(c_y1, jy1), 0.0f);
                    float ww = fmaxf(fminf(c_x2, jx2) - fmaxf(c_x1, jx1), 0.0f);
                    float inter = hh * ww;
                    float uni = c_ar + jar - inter;
                    if (inter > NMS_THRESH * fmaxf(uni, 1e-9f)) bits1 |= (1u << jj);
                }
            }
        }
        u.mat[i0][w] = bits0;
        u.mat[i1][w] = bits1;
        if (bits0) atomicOr(&nzmask[i0 >> 5], 1u << (i0 & 31));
        if (bits1) atomicOr(&nzmask[i1 >> 5], 1u << (i1 & 31));
    }
    __syncthreads();

    // sparse greedy sweep on warp 0
    if (tid < 32) {
        unsigned kw = (tid < 12) ? 0xFFFFFFFFu : ((tid == 12) ? 0xFFFFu : 0u);
        for (int iw = 0; iw < NWORD; iw++) {
            unsigned done = 0u;
            while (true) {
                unsigned wb = __shfl_sync(0xFFFFFFFFu, kw, iw);
                unsigned act = wb & nzmask[iw] & ~done;
                if (act == 0u) break;
                int bit = __ffs(act) - 1;
                done |= (1u << bit);
                int i = iw * 32 + bit;
                if (tid < NWORD) kw &= ~u.mat[i][tid];
            }
        }
        if (tid < NWORD) keepw[tid] = kw;
    }
    __syncthreads();

    float* ks = g_kept_scores + (size_t)bc * PRE_NMS_K;
    unsigned* ki = g_kept_idx + (size_t)bc * PRE_NMS_K;
    for (int t = tid; t < PRE_NMS_K; t += 256) {
        float v = __uint_as_float((unsigned)(cand[t] >> 32));
        int kept = (keepw[t >> 5] >> (t & 31)) & 1;
        ks[t] = (kept && v > 0.0f) ? v : 0.0f;
        ki[t] = 0xFFFFFFFFu - (unsigned)(cand[t] & 0xFFFFFFFFull);
    }
}

// ============================================================
// Kernel 3: per-image top-200
// out layout (float32): bbox[8][200][4] | conf[8][200] | cls[8][200] | num[8]
// ============================================================
__global__ __launch_bounds__(256) void final_kernel(float* __restrict__ out)
{
    __shared__ unsigned hist[2048];
    __shared__ RadixState rst;
    __shared__ unsigned long long cand[512];
    __shared__ int s_cnt, s_nval;

    int tid = threadIdx.x;
    int b = blockIdx.x;
    const float4* sc4 = (const float4*)(g_kept_scores + (size_t)b * FLAT_K);
    const int n4 = FLAT_K / 4;

    unsigned T = radix_thresh(sc4, n4, MAX_BOXES, 512, hist, &rst);

    if (tid == 0) { s_cnt = 0; s_nval = 0; }
    __syncthreads();
    {
        int iters = (n4 + 255) / 256;
        for (int it = 0; it < iters; it++) {
            int i = it * 256 + tid;
            bool valid = i < n4;
            float4 v = valid ? sc4[i] : make_float4(0.f, 0.f, 0.f, 0.f);
            unsigned kk[4] = {__float_as_uint(v.x), __float_as_uint(v.y),
                              __float_as_uint(v.z), __float_as_uint(v.w)};
#pragma unroll
            for (int e = 0; e < 4; e++) {
                bool take = valid && ((T > 0u) ? (kk[e] >= T) : (kk[e] > 0u));
                append_cand(take, kk[e], (unsigned)(i * 4 + e), cand, 512, &s_cnt);
            }
        }
    }
    __syncthreads();
    int cnt = min(s_cnt, 512);
    for (int i = tid; i < 512; i += 256)
        if (i >= cnt) cand[i] = 0ULL;
    bitonic_desc<512>(cand);

    const unsigned* ki = g_kept_idx + (size_t)b * FLAT_K;
    const float4* gb4 = (const float4*)g_boxes + (size_t)b * NANCH;
    for (int t = tid; t < MAX_BOXES; t += 256) {
        unsigned long long e = cand[t];
        float v = __uint_as_float((unsigned)(e >> 32));
        bool valid = v > 0.0f;
        unsigned flat = 0xFFFFFFFFu - (unsigned)(e & 0xFFFFFFFFull);
        float4 bb = make_float4(0.f, 0.f, 0.f, 0.f);
        float clsf = 0.f;
        if (valid) {
            bb = gb4[ki[flat]];
            clsf = (float)(flat / PRE_NMS_K);
            atomicAdd(&s_nval, 1);
        }
        int o = b * MAX_BOXES + t;
        ((float4*)out)[o] = bb;
        out[BATCH * MAX_BOXES * 4 + o] = v;
        out[BATCH * MAX_BOXES * 4 + BATCH * MAX_BOXES + o] = clsf;
    }
    __syncthreads();
    if (tid == 0)
        out[BATCH * MAX_BOXES * 4 + 2 * BATCH * MAX_BOXES + b] = (float)s_nval;
}

// ============================================================
extern "C" void kernel_launch(void* const* d_in, const int* in_sizes, int n_in,
                              void* d_out, int out_size)
{
    const float* p3 = (const float*)d_in[0];
    const float* p4 = (const float*)d_in[1];
    const float* p5 = (const float*)d_in[2];
    const float* a3 = (const float*)d_in[3];
    const float* a4 = (const float*)d_in[4];
    const float* a5 = (const float*)d_in[5];
    float* out = (float*)d_out;

    decode_kernel<<<BATCH * (NANCH / 64), 256>>>(p3, p4, p5, a3, a4, a5);
    percls_kernel<<<BATCH * NUM_CLASSES, 256>>>();
    final_kernel<<<BATCH, 256>>>(out);
}

// round 6
// speedup vs baseline: 2.5701x; 1.1201x over previous
#include <cuda_runtime.h>
#include <cstdint>

#define NUM_CLASSES 80
#define PRE_NMS_K   400
#define MAX_BOXES   200
#define NMS_THRESH  0.6f
#define BATCH       8
#define NANCH       16128   // 64*64*3 + 32*32*3 + 16*16*3
#define FLAT_K      (NUM_CLASSES * PRE_NMS_K)   // 32000
#define C5          85
#define NWORD       13      // ceil(400/32)

typedef unsigned long long ull;

// ---- device scratch ----
__device__ float g_boxes[BATCH * NANCH * 4];                    // (y1,x1,y2,x2) clipped
__device__ float g_scores[BATCH * NUM_CLASSES * NANCH];         // [b][c][n]
__device__ float g_kept_scores[BATCH * NUM_CLASSES * PRE_NMS_K];
__device__ unsigned g_kept_idx[BATCH * NUM_CLASSES * PRE_NMS_K];

__device__ __forceinline__ float sigmoidf(float x) {
    return 1.0f / (1.0f + expf(-x));
}

// ============================================================
// Kernel 1: decode. 64 contiguous anchors per block, float4 I/O.
// ============================================================
__global__ __launch_bounds__(256) void decode_kernel(
    const float* __restrict__ p3, const float* __restrict__ p4, const float* __restrict__ p5,
    const float* __restrict__ a3, const float* __restrict__ a4, const float* __restrict__ a5)
{
    __shared__ float4 tile4[64 * C5 / 4];   // 1360 float4 = 64x85 floats (contiguous)
    __shared__ float s_obj[64];
    float* tile = (float*)tile4;

    int tid = threadIdx.x;
    int blk = blockIdx.x;
    int b  = blk / (NANCH / 64);
    int n0 = (blk % (NANCH / 64)) * 64;

    const float* p; const float* anc;
    int HW; float stride, sxy; int base;
    if (n0 < 12288)      { p = p3; anc = a3; HW = 64; stride = 8.0f;  sxy = 1.20f; base = 0; }
    else if (n0 < 15360) { p = p4; anc = a4; HW = 32; stride = 16.0f; sxy = 1.10f; base = 12288; }
    else                 { p = p5; anc = a5; HW = 16; stride = 32.0f; sxy = 1.05f; base = 15360; }

    int loc0 = n0 - base;
    const float4* src4 = (const float4*)(p + ((size_t)b * HW * HW * 3 + loc0) * C5);

    for (int i = tid; i < 64 * C5 / 4; i += 256) tile4[i] = src4[i];
    __syncthreads();

    if (tid < 64) {
        int loc = loc0 + tid;
        int a  = loc % 3;
        int hw = loc / 3;
        int w  = hw % HW;
        int h  = hw / HW;
        const float* r = &tile[tid * C5];

        float invHW = 1.0f / (float)HW;
        float sx = sigmoidf(r[0]);
        float sy = sigmoidf(r[1]);
        float x = (sx * sxy - 0.5f * (sxy - 1.0f) + (float)w) * invHW;
        float y = (sy * sxy - 0.5f * (sxy - 1.0f) + (float)h) * invHW;

        float denom = 1.0f / ((float)HW * stride);
        float bw = expf(r[2]) * anc[a * 2 + 0] * denom;
        float bh = expf(r[3]) * anc[a * 2 + 1] * denom;

        float y1 = fminf(fmaxf(y - 0.5f * bh, 0.0f), 1.0f);
        float x1 = fminf(fmaxf(x - 0.5f * bw, 0.0f), 1.0f);
        float y2 = fminf(fmaxf(y + 0.5f * bh, 0.0f), 1.0f);
        float x2 = fminf(fmaxf(x + 0.5f * bw, 0.0f), 1.0f);

        ((float4*)g_boxes)[(size_t)b * NANCH + n0 + tid] = make_float4(y1, x1, y2, x2);
        s_obj[tid] = sigmoidf(r[4]);
    }
    __syncthreads();

    size_t sbase = (size_t)b * NUM_CLASSES * NANCH + n0;
    for (int i = tid; i < 64 * NUM_CLASSES / 4; i += 256) {
        int c  = i >> 4;            // class
        int a0 = (i & 15) * 4;      // anchor base
        float4 v;
        v.x = sigmoidf(tile[(a0 + 0) * C5 + 5 + c]) * s_obj[a0 + 0];
        v.y = sigmoidf(tile[(a0 + 1) * C5 + 5 + c]) * s_obj[a0 + 1];
        v.z = sigmoidf(tile[(a0 + 2) * C5 + 5 + c]) * s_obj[a0 + 2];
        v.w = sigmoidf(tile[(a0 + 3) * C5 + 5 + c]) * s_obj[a0 + 3];
        *(float4*)(g_scores + sbase + (size_t)c * NANCH + a0) = v;
    }
}

// ============================================================
// Sampled threshold: histogram every 4th float4 (1/4 of data),
// 2048 bins on bits[30:20]. Picks bucket whose sampled suffix
// count lands in [rlo, rhi]; ok=0 if none (caller falls back).
// ============================================================
struct SampleRes { unsigned T; int ok; };

__device__ void sample_thresh(const float4* __restrict__ sc4, int n4, int rlo, int rhi,
                              unsigned* hist, SampleRes* res)
{
    int tid = threadIdx.x;
    for (int i = tid; i < 2048; i += 256) hist[i] = 0u;
    if (tid == 0) { res->ok = 0; res->T = 0u; }
    __syncthreads();
    int ns = n4 / 4;
    for (int it = tid; it < ns; it += 256) {
        float4 v = sc4[it * 4];
        atomicAdd(&hist[__float_as_uint(v.x) >> 20], 1u);
        atomicAdd(&hist[__float_as_uint(v.y) >> 20], 1u);
        atomicAdd(&hist[__float_as_uint(v.z) >> 20], 1u);
        atomicAdd(&hist[__float_as_uint(v.w) >> 20], 1u);
    }
    __syncthreads();
    if (tid < 32) {
        int lane = tid;
        int hi = 2047 - lane * 64;
        unsigned s = 0;
        for (int e = 0; e < 64; e++) s += hist[hi - e];
        unsigned inc = s;
#pragma unroll
        for (int off = 1; off < 32; off <<= 1) {
            unsigned t2 = __shfl_up_sync(0xFFFFFFFFu, inc, off);
            if (lane >= off) inc += t2;
        }
        unsigned excl = inc - s;
        bool has = (excl < (unsigned)rlo) && (inc >= (unsigned)rlo);
        unsigned ball = __ballot_sync(0xFFFFFFFFu, has);
        if (ball != 0u && lane == (__ffs(ball) - 1)) {
            unsigned cum = excl;
            for (int e = 0; e < 64; e++) {
                unsigned h = hist[hi - e];
                if (cum + h >= (unsigned)rlo) {
                    if (cum + h <= (unsigned)rhi) {
                        res->T = (unsigned)(hi - e) << 20;
                        res->ok = 1;
                    }
                    break;
                }
                cum += h;
            }
        }
    }
    __syncthreads();
}

// ============================================================
// Exact adaptive radix threshold (fallback path).
// ============================================================
struct RadixState { unsigned prefix, T; int rem, done; };

__device__ unsigned radix_thresh(const float4* __restrict__ sc4, int n4, int K, int cap,
                                 unsigned* hist /*2048*/, RadixState* st)
{
    int tid = threadIdx.x;
    int lane = tid & 31;
    if (tid == 0) { st->prefix = 0u; st->rem = K; st->done = 0; }
    int iters = (n4 + 255) / 256;

    for (int lvl = 0; lvl < 3; lvl++) {
        const int shift = (lvl == 0) ? 20 : ((lvl == 1) ? 10 : 0);
        const int bins  = (lvl == 0) ? 2048 : 1024;
        for (int i = tid; i < bins; i += 256) hist[i] = 0u;
        __syncthreads();
        unsigned pref = st->prefix;
        for (int it = 0; it < iters; it++) {
            int i = it * 256 + tid;
            if (i < n4) {
                float4 v = sc4[i];
                unsigned kk[4] = {__float_as_uint(v.x), __float_as_uint(v.y),
                                  __float_as_uint(v.z), __float_as_uint(v.w)};
#pragma unroll
                for (int e = 0; e < 4; e++) {
                    unsigned k = kk[e];
                    if (lvl == 0 || (k >> (shift + 10)) == pref)
                        atomicAdd(&hist[(k >> shift) & (bins - 1)], 1u);
                }
            }
        }
        __syncthreads();
        if (tid < 32) {
            int per = bins / 32;
            int hi = bins - 1 - lane * per;
            unsigned s = 0;
            for (int e = 0; e < per; e++) s += hist[hi - e];
            unsigned inc = s;
#pragma unroll
            for (int off = 1; off < 32; off <<= 1) {
                unsigned t2 = __shfl_up_sync(0xFFFFFFFFu, inc, off);
                if (lane >= off) inc += t2;
            }
            unsigned excl = inc - s;
            int rem = st->rem;
            bool has = (excl < (unsigned)rem) && ((unsigned)rem <= inc);
            unsigned ball = __ballot_sync(0xFFFFFFFFu, has);
            int ldr = (ball == 0u) ? 31 : (__ffs(ball) - 1);
            if (lane == ldr) {
                unsigned cum = excl;
                int bkt = hi - per + 1;
                unsigned bcount = 0u;
                for (int e = 0; e < per; e++) {
                    unsigned h = hist[hi - e];
                    if (cum + h >= (unsigned)rem) { bkt = hi - e; bcount = h; break; }
                    cum += h;
                }
                unsigned newpref = (lvl == 0) ? (unsigned)bkt
                                              : ((pref << 10) | (unsigned)bkt);
                int tot = (K - rem) + (int)cum + (int)bcount;
                if (tot <= cap || lvl == 2) {
                    st->T = newpref << shift;
                    st->done = 1;
                } else {
                    st->prefix = newpref;
                    st->rem = rem - (int)cum;
                }
            }
        }
        __syncthreads();
        if (st->done) break;
    }
    return st->T;
}

// ============================================================
// Compaction: keep k >= T (or k > 0 when T == 0). One warp-scan
// + one atomic per warp per float4 batch. Returns TOTAL count
// (may exceed cap; writes guarded at cap).
// ============================================================
__device__ int compact_pass(const float4* __restrict__ sc4, int n4, unsigned T,
                            ull* cand, int cap, int* s_cnt)
{
    int tid = threadIdx.x;
    int lane = tid & 31;
    if (tid == 0) *s_cnt = 0;
    __syncthreads();
    int iters = (n4 + 255) / 256;
    for (int it = 0; it < iters; it++) {
        int i = it * 256 + tid;
        unsigned kk[4] = {0u, 0u, 0u, 0u};
        bool tk[4] = {false, false, false, false};
        if (i < n4) {
            float4 v = sc4[i];
            kk[0] = __float_as_uint(v.x); kk[1] = __float_as_uint(v.y);
            kk[2] = __float_as_uint(v.z); kk[3] = __float_as_uint(v.w);
#pragma unroll
            for (int e = 0; e < 4; e++)
                tk[e] = (T > 0u) ? (kk[e] >= T) : (kk[e] > 0u);
        }
        int c = (int)tk[0] + (int)tk[1] + (int)tk[2] + (int)tk[3];
        int pre = c;
#pragma unroll
        for (int off = 1; off < 32; off <<= 1) {
            int t2 = __shfl_up_sync(0xFFFFFFFFu, pre, off);
            if (lane >= off) pre += t2;
        }
        int base;
        if (lane == 31) base = atomicAdd(s_cnt, pre);
        base = __shfl_sync(0xFFFFFFFFu, base, 31);
        int pos = base + pre - c;
#pragma unroll
        for (int e = 0; e < 4; e++) {
            if (tk[e]) {
                if (pos < cap)
                    cand[pos] = ((ull)kk[e] << 32) |
                                (ull)(0xFFFFFFFFu - (unsigned)(i * 4 + e));
                pos++;
            }
        }
    }
    __syncthreads();
    return *s_cnt;
}

// descending bitonic sort, pair-index form: all threads active
template <int SIZE>
__device__ void bitonic_desc(ull* a)
{
    int tid = threadIdx.x;
    for (int k = 2; k <= SIZE; k <<= 1) {
        for (int j = k >> 1; j > 0; j >>= 1) {
            __syncthreads();
            for (int p = tid; p < SIZE / 2; p += 256) {
                int i   = ((p & ~(j - 1)) << 1) | (p & (j - 1));
                int ixj = i | j;
                bool seg = (i & k) == 0;
                ull x = a[i], y = a[ixj];
                if (seg ? (x < y) : (x > y)) { a[i] = y; a[ixj] = x; }
            }
        }
    }
    __syncthreads();
}

// ============================================================
// Kernel 2: per (b, class) top-400 + greedy NMS
// ============================================================
__global__ __launch_bounds__(256) void percls_kernel()
{
    __shared__ union {
        unsigned hist[2048];                 // threshold phase
        unsigned mat[PRE_NMS_K][NWORD];      // NMS phase
    } u;
    __shared__ SampleRes sres;
    __shared__ RadixState rst;
    __shared__ ull cand[1024];
    __shared__ int s_cnt;
    __shared__ float bx0[PRE_NMS_K], bx1[PRE_NMS_K], bx2[PRE_NMS_K], bx3[PRE_NMS_K], ar[PRE_NMS_K];
    __shared__ unsigned nzmask[NWORD];
    __shared__ unsigned keepw[NWORD];

    int tid = threadIdx.x;
    int bc = blockIdx.x;
    int b = bc / NUM_CLASSES;
    const float4* sc4 = (const float4*)(g_scores + (size_t)bc * NANCH);
    const int n4 = NANCH / 4;

    sample_thresh(sc4, n4, 140, 210, u.hist, &sres);
    unsigned T = sres.T;
    int cnt = 0;
    if (sres.ok) cnt = compact_pass(sc4, n4, T, cand, 1024, &s_cnt);
    if (!sres.ok || cnt < PRE_NMS_K || cnt > 1024) {
        T = radix_thresh(sc4, n4, PRE_NMS_K, 1024, u.hist, &rst);
        cnt = compact_pass(sc4, n4, T, cand, 1024, &s_cnt);
    }
    cnt = min(cnt, 1024);

    if (cnt <= 512) {
        for (int i = tid; i < 512; i += 256) if (i >= cnt) cand[i] = 0ULL;
        bitonic_desc<512>(cand);
    } else {
        for (int i = tid; i < 1024; i += 256) if (i >= cnt) cand[i] = 0ULL;
        bitonic_desc<1024>(cand);
    }

    // gather boxes of sorted top-400
    const float4* gb4 = (const float4*)g_boxes + (size_t)b * NANCH;
    for (int t = tid; t < PRE_NMS_K; t += 256) {
        unsigned idx = 0xFFFFFFFFu - (unsigned)(cand[t] & 0xFFFFFFFFull);
        float4 bp = gb4[idx];
        bx0[t] = bp.x; bx1[t] = bp.y; bx2[t] = bp.z; bx3[t] = bp.w;
        ar[t] = (bp.z - bp.x) * (bp.w - bp.y);
    }
    if (tid < NWORD) nzmask[tid] = 0u;
    __syncthreads();

    // suppression bitmask, atomic-free, 2-row register tiling
    for (int p = tid; p < (PRE_NMS_K / 2) * NWORD; p += 256) {
        int i2 = p % (PRE_NMS_K / 2);
        int w  = p / (PRE_NMS_K / 2);
        int i0 = i2 * 2;
        int i1 = i0 + 1;
        int jbase = w * 32;
        unsigned bits0 = 0u, bits1 = 0u;
        if (jbase + 31 > i0) {
            float a_y1 = bx0[i0], a_x1 = bx1[i0], a_y2 = bx2[i0], a_x2 = bx3[i0], a_ar = ar[i0];
            float c_y1 = bx0[i1], c_x1 = bx1[i1], c_y2 = bx2[i1], c_x2 = bx3[i1], c_ar = ar[i1];
            int jend = min(32, PRE_NMS_K - jbase);
            for (int jj = 0; jj < jend; jj++) {
                int j = jbase + jj;
                float jy1 = bx0[j], jx1 = bx1[j], jy2 = bx2[j], jx2 = bx3[j], jar = ar[j];
                if (j > i0) {
                    float hh = fmaxf(fminf(a_y2, jy2) - fmaxf(a_y1, jy1), 0.0f);
                    float ww = fmaxf(fminf(a_x2, jx2) - fmaxf(a_x1, jx1), 0.0f);
                    float inter = hh * ww;
                    float uni = a_ar + jar - inter;
                    if (inter > NMS_THRESH * fmaxf(uni, 1e-9f)) bits0 |= (1u << jj);
                }
                if (j > i1) {
                    float hh = fmaxf(fminf(c_y2, jy2) - fmaxf(c_y1, jy1), 0.0f);
                    float ww = fmaxf(fminf(c_x2, jx2) - fmaxf(c_x1, jx1), 0.0f);
                    float inter = hh * ww;
                    float uni = c_ar + jar - inter;
                    if (inter > NMS_THRESH * fmaxf(uni, 1e-9f)) bits1 |= (1u << jj);
                }
            }
        }
        u.mat[i0][w] = bits0;
        u.mat[i1][w] = bits1;
        if (bits0) atomicOr(&nzmask[i0 >> 5], 1u << (i0 & 31));
        if (bits1) atomicOr(&nzmask[i1 >> 5], 1u << (i1 & 31));
    }
    __syncthreads();

    // sparse greedy sweep on warp 0
    if (tid < 32) {
        unsigned kw = (tid < 12) ? 0xFFFFFFFFu : ((tid == 12) ? 0xFFFFu : 0u);
        for (int iw = 0; iw < NWORD; iw++) {
            unsigned done = 0u;
            while (true) {
                unsigned wb = __shfl_sync(0xFFFFFFFFu, kw, iw);
                unsigned act = wb & nzmask[iw] & ~done;
                if (act == 0u) break;
                int bit = __ffs(act) - 1;
                done |= (1u << bit);
                int i = iw * 32 + bit;
                if (tid < NWORD) kw &= ~u.mat[i][tid];
            }
        }
        if (tid < NWORD) keepw[tid] = kw;
    }
    __syncthreads();

    float* ks = g_kept_scores + (size_t)bc * PRE_NMS_K;
    unsigned* ki = g_kept_idx + (size_t)bc * PRE_NMS_K;
    for (int t = tid; t < PRE_NMS_K; t += 256) {
        float v = __uint_as_float((unsigned)(cand[t] >> 32));
        int kept = (keepw[t >> 5] >> (t & 31)) & 1;
        ks[t] = (kept && v > 0.0f) ? v : 0.0f;
        ki[t] = 0xFFFFFFFFu - (unsigned)(cand[t] & 0xFFFFFFFFull);
    }
}

// ============================================================
// Kernel 3: per-image top-200
// out layout (float32): bbox[8][200][4] | conf[8][200] | cls[8][200] | num[8]
// ============================================================
__global__ __launch_bounds__(256) void final_kernel(float* __restrict__ out)
{
    __shared__ unsigned hist[2048];
    __shared__ SampleRes sres;
    __shared__ RadixState rst;
    __shared__ ull cand[512];
    __shared__ int s_cnt, s_nval;

    int tid = threadIdx.x;
    int b = blockIdx.x;
    const float4* sc4 = (const float4*)(g_kept_scores + (size_t)b * FLAT_K);
    const int n4 = FLAT_K / 4;

    sample_thresh(sc4, n4, 75, 105, hist, &sres);
    unsigned T = sres.T;
    int cnt = 0;
    if (sres.ok) cnt = compact_pass(sc4, n4, T, cand, 512, &s_cnt);
    if (!sres.ok || cnt < MAX_BOXES || cnt > 512) {
        T = radix_thresh(sc4, n4, MAX_BOXES, 512, hist, &rst);
        cnt = compact_pass(sc4, n4, T, cand, 512, &s_cnt);
    }
    cnt = min(cnt, 512);

    for (int i = tid; i < 512; i += 256)
        if (i >= cnt) cand[i] = 0ULL;
    bitonic_desc<512>(cand);

    if (tid == 0) s_nval = 0;
    __syncthreads();

    const unsigned* ki = g_kept_idx + (size_t)b * FLAT_K;
    const float4* gb4 = (const float4*)g_boxes + (size_t)b * NANCH;
    for (int t = tid; t < MAX_BOXES; t += 256) {
        ull e = cand[t];
        float v = __uint_as_float((unsigned)(e >> 32));
        bool valid = v > 0.0f;
        unsigned flat = 0xFFFFFFFFu - (unsigned)(e & 0xFFFFFFFFull);
        float4 bb = make_float4(0.f, 0.f, 0.f, 0.f);
        float clsf = 0.f;
        if (valid) {
            bb = gb4[ki[flat]];
            clsf = (float)(flat / PRE_NMS_K);
            atomicAdd(&s_nval, 1);
        }
        int o = b * MAX_BOXES + t;
        ((float4*)out)[o] = bb;
        out[BATCH * MAX_BOXES * 4 + o] = v;
        out[BATCH * MAX_BOXES * 4 + BATCH * MAX_BOXES + o] = clsf;
    }
    __syncthreads();
    if (tid == 0)
        out[BATCH * MAX_BOXES * 4 + 2 * BATCH * MAX_BOXES + b] = (float)s_nval;
}

// ============================================================
extern "C" void kernel_launch(void* const* d_in, const int* in_sizes, int n_in,
                              void* d_out, int out_size)
{
    const float* p3 = (const float*)d_in[0];
    const float* p4 = (const float*)d_in[1];
    const float* p5 = (const float*)d_in[2];
    const float* a3 = (const float*)d_in[3];
    const float* a4 = (const float*)d_in[4];
    const float* a5 = (const float*)d_in[5];
    float* out = (float*)d_out;

    decode_kernel<<<BATCH * (NANCH / 64), 256>>>(p3, p4, p5, a3, a4, a5);
    percls_kernel<<<BATCH * NUM_CLASSES, 256>>>();
    final_kernel<<<BATCH, 256>>>(out);
}